// round 10
// baseline (speedup 1.0000x reference)
#include <cuda_runtime.h>

// Fixed shapes: B=8, H=8, S=16384, Dv=64, d_k=1
#define BH      64
#define SEQ     16384
#define DV      64
#define NSPLIT  32
#define CHUNK   (SEQ / NSPLIT)   // 512 rows per split
#define PSTRIDE 68               // 64 ktv + ksq + qsq, padded to float4 stride

__device__ float g_part[BH * NSPLIT * PSTRIDE];

// ---------------------------------------------------------------------------
// Kernel 1: per-(bh, split) partial reduction, 512-row chunks (2048 CTAs =
// 1.73 resident waves -> wave-2 backfills the CTA-spread tail).
// ---------------------------------------------------------------------------
__global__ __launch_bounds__(256) void reduce_kernel(
    const float* __restrict__ Q,
    const float* __restrict__ K,
    const float* __restrict__ V)
{
    const int bh    = blockIdx.x / NSPLIT;
    const int split = blockIdx.x % NSPLIT;
    const int t     = threadIdx.x;
    const int colg  = t & 15;
    const int rowg  = t >> 4;

    const float4* __restrict__ Vp4 =
        reinterpret_cast<const float4*>(V + (size_t)bh * SEQ * DV + (size_t)(split * CHUNK) * DV);
    const float4* __restrict__ Kp4 =
        reinterpret_cast<const float4*>(K + bh * SEQ + split * CHUNK);
    const float4* __restrict__ Qp4 =
        reinterpret_cast<const float4*>(Q + bh * SEQ + split * CHUNK);

    __shared__ float sK[CHUNK];

    // Stage K chunk (512 floats) with 128 threads; ksq/qsq partials uniform.
    float ksq = 0.f, qsq = 0.f;
    if (t < CHUNK / 4) {
        float4 kv = Kp4[t];
        reinterpret_cast<float4*>(sK)[t] = kv;
        ksq = kv.x * kv.x + kv.y * kv.y + kv.z * kv.z + kv.w * kv.w;
        float4 qv = Qp4[t];
        qsq = qv.x * qv.x + qv.y * qv.y + qv.z * qv.z + qv.w * qv.w;
    }
    __syncthreads();

    float4 a0 = make_float4(0.f, 0.f, 0.f, 0.f);
    float4 a1 = make_float4(0.f, 0.f, 0.f, 0.f);

    // 16 bodies of 2 independent loads; unroll 4 -> 8 loads in flight.
    #pragma unroll 4
    for (int r = rowg; r < CHUNK; r += 32) {
        float  k0 = sK[r];
        float4 v0 = __ldcs(&Vp4[(size_t)r * 16 + colg]);
        float  k1 = sK[r + 16];
        float4 v1 = __ldcs(&Vp4[(size_t)(r + 16) * 16 + colg]);
        a0.x += k0 * v0.x;  a0.y += k0 * v0.y;  a0.z += k0 * v0.z;  a0.w += k0 * v0.w;
        a1.x += k1 * v1.x;  a1.y += k1 * v1.y;  a1.z += k1 * v1.z;  a1.w += k1 * v1.w;
    }
    a0.x += a1.x; a0.y += a1.y; a0.z += a1.z; a0.w += a1.w;

    // Fold the two row-groups within each warp (lane ^ 16 has same colg).
    a0.x += __shfl_xor_sync(0xFFFFFFFFu, a0.x, 16);
    a0.y += __shfl_xor_sync(0xFFFFFFFFu, a0.y, 16);
    a0.z += __shfl_xor_sync(0xFFFFFFFFu, a0.z, 16);
    a0.w += __shfl_xor_sync(0xFFFFFFFFu, a0.w, 16);

    #pragma unroll
    for (int m = 16; m >= 1; m >>= 1) {
        ksq += __shfl_xor_sync(0xFFFFFFFFu, ksq, m);
        qsq += __shfl_xor_sync(0xFFFFFFFFu, qsq, m);
    }

    __shared__ float4 s_acc[8][16];
    __shared__ float  s_ksq[8];
    __shared__ float  s_qsq[8];
    const int warp = t >> 5;
    const int lane = t & 31;
    if (lane < 16) s_acc[warp][lane] = a0;
    if (lane == 0) { s_ksq[warp] = ksq; s_qsq[warp] = qsq; }
    __syncthreads();

    float* __restrict__ outp = g_part + (size_t)(bh * NSPLIT + split) * PSTRIDE;
    if (t < 16) {
        float4 a = s_acc[0][t];
        #pragma unroll
        for (int w = 1; w < 8; ++w) {
            float4 b = s_acc[w][t];
            a.x += b.x; a.y += b.y; a.z += b.z; a.w += b.w;
        }
        reinterpret_cast<float4*>(outp)[t] = a;
    } else if (t == 16) {
        float a = 0.f, b = 0.f;
        #pragma unroll
        for (int w = 0; w < 8; ++w) { a += s_ksq[w]; b += s_qsq[w]; }
        outp[64] = a;
        outp[65] = b;
    }
}

// ---------------------------------------------------------------------------
// Kernel 2 (fused combine + broadcast): exact R3 version (41.8us @ 6.2TB/s).
// ---------------------------------------------------------------------------
#define BROWS 256
__global__ __launch_bounds__(256) void broadcast_kernel(
    const float* __restrict__ Q,
    float* __restrict__ out)
{
    const size_t row0 = (size_t)blockIdx.x * BROWS;  // 256 | 16384 -> single bh
    const int    t    = threadIdx.x;
    const int    bh   = (int)(row0 >> 14);

    __shared__ float s_coef[DV];
    __shared__ float s_scale;
    __shared__ float sQ[BROWS];

    sQ[t] = Q[row0 + t];

    const float* __restrict__ base = g_part + (size_t)bh * NSPLIT * PSTRIDE;
    if (t < DV) {
        float ktv = 0.f;
        #pragma unroll
        for (int s = 0; s < NSPLIT; ++s) ktv += base[(size_t)s * PSTRIDE + t];
        s_coef[t] = ktv;
    } else if (t == DV) {
        float ksq = 0.f, qsq = 0.f;
        #pragma unroll
        for (int s = 0; s < NSPLIT; ++s) {
            ksq += base[(size_t)s * PSTRIDE + 64];
            qsq += base[(size_t)s * PSTRIDE + 65];
        }
        s_scale = 1.0f / (sqrtf(ksq) * sqrtf(qsq));
    }
    __syncthreads();

    const int rg = t >> 4;
    const int cg = t & 15;
    const float scale = s_scale;
    float4 c = reinterpret_cast<const float4*>(s_coef)[cg];
    c.x *= scale; c.y *= scale; c.z *= scale; c.w *= scale;

    #pragma unroll
    for (int ri = 0; ri < BROWS / 16; ++ri) {
        const int    lr  = ri * 16 + rg;
        const size_t row = row0 + lr;
        const float  q   = sQ[lr];
        float4 o;
        o.x = q * c.x;
        o.y = q * c.y;
        o.z = q * c.z;
        o.w = q * c.w;
        __stcs(reinterpret_cast<float4*>(out) + row * 16 + cg, o);
    }
}

// ---------------------------------------------------------------------------
extern "C" void kernel_launch(void* const* d_in, const int* in_sizes, int n_in,
                              void* d_out, int out_size)
{
    const float* Q = (const float*)d_in[0];
    const float* K = (const float*)d_in[1];
    const float* V = (const float*)d_in[2];
    float* out = (float*)d_out;

    reduce_kernel<<<BH * NSPLIT, 256>>>(Q, K, V);
    broadcast_kernel<<<(BH * SEQ) / BROWS, 256>>>(Q, out);
}